// round 17
// baseline (speedup 1.0000x reference)
#include <cuda_runtime.h>
#include <cuda_fp16.h>
#include <math.h>
#include <stdint.h>

// ---------------- problem constants ----------------
#define S_LEN   2048
#define HID     3584
#define NHQ     16
#define NKV     8
#define DH      256
#define GROUPS  2
#define WINDOW  1024
#define BANDW   1152
#define SOFTCAP 50.0f
#define SCALING 0.0625f

typedef __half h16;

// ---------------- device scratch ----------------
__device__ float g_Q [(size_t)S_LEN * NHQ * DH];
__device__ float g_K [(size_t)S_LEN * NKV * DH];
__device__ float g_V [(size_t)S_LEN * NKV * DH];
__device__ float g_S [(size_t)NHQ * S_LEN * BANDW];

__device__ h16 g_hsH[(size_t)S_LEN * HID],      g_hsL[(size_t)S_LEN * HID];
__device__ h16 g_wqH[(size_t)NHQ * DH * HID];
__device__ h16 g_wkH[(size_t)NKV * DH * HID];
__device__ h16 g_wvH[(size_t)NKV * DH * HID];
__device__ h16 g_woH[(size_t)HID * NHQ * DH];
__device__ h16 g_QH [(size_t)S_LEN * NHQ * DH], g_QL [(size_t)S_LEN * NHQ * DH];
__device__ h16 g_KH [(size_t)S_LEN * NKV * DH];
__device__ h16 g_VtH[(size_t)NKV * DH * S_LEN];
__device__ h16 g_PH [(size_t)NHQ * S_LEN * BANDW];
__device__ h16 g_AOH[(size_t)S_LEN * NHQ * DH];

// ---------------- helpers ----------------
__device__ __forceinline__ uint32_t smem_u32(const void* p) {
    uint32_t a;
    asm("{ .reg .u64 t; cvta.to.shared.u64 t, %1; cvt.u32.u64 %0, t; }" : "=r"(a) : "l"(p));
    return a;
}
__device__ __forceinline__ void cp16(uint32_t saddr, const void* g) {
    asm volatile("cp.async.cg.shared.global [%0], [%1], 16;" :: "r"(saddr), "l"(g) : "memory");
}
#define CP_COMMIT() asm volatile("cp.async.commit_group;" ::: "memory")

#define LDSM4(r0, r1, r2, r3, addr) \
    asm volatile("ldmatrix.sync.aligned.m8n8.x4.shared.b16 {%0,%1,%2,%3}, [%4];" \
        : "=r"(r0), "=r"(r1), "=r"(r2), "=r"(r3) : "r"(addr))

__device__ __forceinline__ void mma32(float* c,
    uint32_t a0, uint32_t a1, uint32_t a2, uint32_t a3,
    uint32_t b0, uint32_t b1)
{
    asm volatile(
        "mma.sync.aligned.m16n8k16.row.col.f32.f16.f16.f32 "
        "{%0,%1,%2,%3}, {%4,%5,%6,%7}, {%8,%9}, {%0,%1,%2,%3};"
        : "+f"(c[0]), "+f"(c[1]), "+f"(c[2]), "+f"(c[3])
        : "r"(a0), "r"(a1), "r"(a2), "r"(a3), "r"(b0), "r"(b1));
}

// ---------------- generic stage layout ----------------
// CK = K elements per stage (64 or 32). Row pitch = 2*CK bytes. SEGS = pitch/16.
// Swizzle: CK64: seg ^ (row & 7); CK32: seg ^ ((row>>1) & 3).
// Arrays: Ah [+ Al if NPROD==2] + Bh, each 128*pitch bytes.
#define NSTAGE 3

template <int NPROD, int CK>
__device__ __forceinline__ void stage_cp(
    const h16* __restrict__ Ah, const h16* __restrict__ Al, int lda,
    const h16* __restrict__ Bh, int ldb,
    int k0, uint32_t smb, int buf, int tid)
{
    const int PITCH  = 2 * CK;
    const int SEGS   = PITCH / 16;
    const int SH     = (CK == 64) ? 0 : 1;
    const int ABYTES = 128 * PITCH;
    const int STG    = ABYTES * (NPROD + 1);
    const uint32_t OBH = (uint32_t)ABYTES * NPROD;
    uint32_t sb = smb + buf * STG;
#pragma unroll
    for (int i = 0; i < SEGS; ++i) {
        int si  = tid + i * 128;
        int row = si / SEGS;
        int seg = si % SEGS;
        uint32_t soff = row * PITCH + ((seg ^ ((row >> SH) & (SEGS - 1))) << 4);
        size_t goA = (size_t)row * lda + k0 + seg * 8;
        size_t goB = (size_t)row * ldb + k0 + seg * 8;
        cp16(sb + soff, Ah + goA);
        if (NPROD == 2) cp16(sb + ABYTES + soff, Al + goA);
        cp16(sb + OBH + soff, Bh + goB);
    }
}

// ---------------- 128x128 NT GEMM tile, fp16, fp32 accum ----------------
// 128 threads (4 warps, 2x2, warp tile 64x64). K % CK == 0.
// NPROD=2: Ah*Bh + Al*Bh.  NPROD=1: Ah*Bh.
// EPI=0: fp32 C.  EPI=2: fp16 hi only (Ch).
template <int NPROD, int EPI, int CK>
__device__ void gemm_tile(
    const h16* __restrict__ Ah, const h16* __restrict__ Al, int lda,
    const h16* __restrict__ Bh, int ldb,
    float* __restrict__ C, h16* __restrict__ Ch,
    int ldc, int K)
{
    const int PITCH  = 2 * CK;
    const int SEGS   = PITCH / 16;
    const int SH     = (CK == 64) ? 0 : 1;
    const int ABYTES = 128 * PITCH;
    const int STG    = ABYTES * (NPROD + 1);
    const uint32_t OBH = (uint32_t)ABYTES * NPROD;
    extern __shared__ char smem[];
    const uint32_t smb = smem_u32(smem);
    const int tid  = threadIdx.x;
    const int lane = tid & 31;
    const int wid  = tid >> 5;
    const int wm   = wid >> 1;
    const int wn   = wid & 1;
    const int la   = lane & 7;
    const int grp  = lane >> 3;

    float acc[4][8][4];
#pragma unroll
    for (int mi = 0; mi < 4; ++mi)
#pragma unroll
        for (int ni = 0; ni < 8; ++ni)
#pragma unroll
            for (int q = 0; q < 4; ++q) acc[mi][ni][q] = 0.0f;

    uint32_t offA[4], swA[4];
#pragma unroll
    for (int mi = 0; mi < 4; ++mi) {
        int r = wm * 64 + mi * 16 + la + (grp & 1) * 8;
        offA[mi] = r * PITCH;
        swA[mi]  = (r >> SH) & (SEGS - 1);
    }
    const int segselA = grp >> 1;
    uint32_t offB[4], swB[4];
#pragma unroll
    for (int p = 0; p < 4; ++p) {
        int r = wn * 64 + p * 16 + la + (grp >> 1) * 8;
        offB[p] = r * PITCH;
        swB[p]  = (r >> SH) & (SEGS - 1);
    }
    const int segselB = grp & 1;

    const int nK = K / CK;
    stage_cp<NPROD, CK>(Ah, Al, lda, Bh, ldb, 0, smb, 0, tid);
    CP_COMMIT();
    stage_cp<NPROD, CK>(Ah, Al, lda, Bh, ldb, CK, smb, 1, tid);
    CP_COMMIT();

    for (int ki = 0; ki < nK; ++ki) {
        asm volatile("cp.async.wait_group 1;" ::: "memory");   // stage ki arrived
        __syncthreads();                                       // prior consume done
        if (ki + 2 < nK)
            stage_cp<NPROD, CK>(Ah, Al, lda, Bh, ldb, (ki + 2) * CK, smb, (ki + 2) % NSTAGE, tid);
        CP_COMMIT();

        const uint32_t sA  = smb + (ki % NSTAGE) * STG;
        const uint32_t sAl = sA + ABYTES;
        const uint32_t sB  = sA + OBH;

#pragma unroll
        for (int ks = 0; ks < CK / 16; ++ks) {
            uint32_t ah[4][4], al[4][4];
#pragma unroll
            for (int mi = 0; mi < 4; ++mi) {
                uint32_t aoff = offA[mi] + ((((uint32_t)(ks * 2 + segselA) ^ swA[mi])) << 4);
                LDSM4(ah[mi][0], ah[mi][1], ah[mi][2], ah[mi][3], sA + aoff);
                if (NPROD == 2) { LDSM4(al[mi][0], al[mi][1], al[mi][2], al[mi][3], sAl + aoff); }
            }
#pragma unroll
            for (int p = 0; p < 4; ++p) {
                uint32_t boff = offB[p] + ((((uint32_t)(ks * 2 + segselB) ^ swB[p])) << 4);
                uint32_t bh0, bh1, bh2, bh3;
                LDSM4(bh0, bh1, bh2, bh3, sB + boff);
#pragma unroll
                for (int mi = 0; mi < 4; ++mi) {
                    mma32(acc[mi][2 * p],     ah[mi][0], ah[mi][1], ah[mi][2], ah[mi][3], bh0, bh1);
                    mma32(acc[mi][2 * p + 1], ah[mi][0], ah[mi][1], ah[mi][2], ah[mi][3], bh2, bh3);
                }
                if (NPROD == 2) {
#pragma unroll
                    for (int mi = 0; mi < 4; ++mi) {
                        mma32(acc[mi][2 * p],     al[mi][0], al[mi][1], al[mi][2], al[mi][3], bh0, bh1);
                        mma32(acc[mi][2 * p + 1], al[mi][0], al[mi][1], al[mi][2], al[mi][3], bh2, bh3);
                    }
                }
            }
        }
    }

    const int g  = lane >> 2;
    const int t4 = lane & 3;
#pragma unroll
    for (int mi = 0; mi < 4; ++mi) {
        int R0 = wm * 64 + mi * 16 + g;
        int R1 = R0 + 8;
#pragma unroll
        for (int ni = 0; ni < 8; ++ni) {
            int col = wn * 64 + ni * 8 + t4 * 2;
            float* a = acc[mi][ni];
            if (EPI == 0) {
                *(float2*)(C + (size_t)R0 * ldc + col) = make_float2(a[0], a[1]);
                *(float2*)(C + (size_t)R1 * ldc + col) = make_float2(a[2], a[3]);
            } else {
                __half2 H0; H0.x = __float2half(a[0]); H0.y = __float2half(a[1]);
                __half2 H1; H1.x = __float2half(a[2]); H1.y = __float2half(a[3]);
                *(__half2*)(Ch + (size_t)R0 * ldc + col) = H0;
                *(__half2*)(Ch + (size_t)R1 * ldc + col) = H1;
            }
        }
    }
}

// ---------------- GEMM wrapper kernels ----------------
#define SMEM2 (NSTAGE * 49152)   // NPROD2, CK64: 3 x 48 KB
#define SMEM1 (NSTAGE * 16384)   // NPROD1, CK32: 3 x 16 KB

// Fused QKV projection: grid (64, 16). bx 0..31 -> Q (2-prod), 32..47 -> K (2-prod),
// 48..63 -> V (1-prod, also CK64 with NPROD1 layout -> 32 KB stages fits in SMEM2).
__global__ void __launch_bounds__(128, 2)
k_gemm_qkv()
{
    int bx = blockIdx.x, by = blockIdx.y;
    size_t m0 = (size_t)by * 128;
    if (bx < 32) {
        gemm_tile<2, 0, 64>(g_hsH + m0 * HID, g_hsL + m0 * HID, HID,
                            g_wqH + (size_t)bx * 128 * HID, HID,
                            g_Q + m0 * (NHQ * DH) + (size_t)bx * 128, nullptr, NHQ * DH, HID);
    } else if (bx < 48) {
        int b = bx - 32;
        gemm_tile<2, 0, 64>(g_hsH + m0 * HID, g_hsL + m0 * HID, HID,
                            g_wkH + (size_t)b * 128 * HID, HID,
                            g_K + m0 * (NKV * DH) + (size_t)b * 128, nullptr, NKV * DH, HID);
    } else {
        int b = bx - 48;
        gemm_tile<1, 0, 64>(g_hsH + m0 * HID, nullptr, HID,
                            g_wvH + (size_t)b * 128 * HID, HID,
                            g_V + m0 * (NKV * DH) + (size_t)b * 128, nullptr, NKV * DH, HID);
    }
}

// O projection: 1-product, CK32, occ 3
__global__ void __launch_bounds__(128, 3)
k_gemm_o(float* __restrict__ out)
{
    size_t m0 = (size_t)blockIdx.y * 128, n0 = (size_t)blockIdx.x * 128;
    gemm_tile<1, 0, 32>(g_AOH + m0 * (NHQ * DH), nullptr, NHQ * DH,
                        g_woH + n0 * (NHQ * DH), NHQ * DH,
                        out + m0 * HID + n0, nullptr, HID, NHQ * DH);
}

// banded scores: 2-product (Q split x K hi), CK64
__global__ void __launch_bounds__(128, 2)
k_attn_s()
{
    int h = blockIdx.z, r = blockIdx.y, cx = blockIdx.x;
    int cbase = (r - 8 > 0) ? (r - 8) : 0;
    int ct = cbase + cx;
    if (ct > r) return;
    size_t aoff = (size_t)r * 128 * (NHQ * DH) + (size_t)h * DH;
    size_t boff = (size_t)ct * 128 * (NKV * DH) + (size_t)(h / GROUPS) * DH;
    float* C = g_S + ((size_t)h * S_LEN + (size_t)r * 128) * BANDW + (size_t)cx * 128;
    gemm_tile<2, 0, 64>(g_QH + aoff, g_QL + aoff, NHQ * DH,
                        g_KH + boff, NKV * DH,
                        C, nullptr, BANDW, DH);
}

// PV: 1-product (P hi x Vt hi) -> AO hi, CK32, occ 3
__global__ void __launch_bounds__(128, 3)
k_attn_pv()
{
    int h = blockIdx.z, r = blockIdx.y, nx = blockIdx.x;
    int c0 = ((r - 8 > 0) ? (r - 8) : 0) * 128;
    size_t aoff = ((size_t)h * S_LEN + (size_t)r * 128) * BANDW;
    size_t boff = ((size_t)(h / GROUPS) * DH + (size_t)nx * 128) * S_LEN + (size_t)c0;
    size_t coff = (size_t)r * 128 * (NHQ * DH) + (size_t)h * DH + (size_t)nx * 128;
    gemm_tile<1, 2, 32>(g_PH + aoff, nullptr, BANDW,
                        g_VtH + boff, S_LEN,
                        nullptr, g_AOH + coff, NHQ * DH, BANDW);
}

// ---------------- fused split of all 5 inputs ----------------
#define N_HS 1835008   // 2048*3584/4
#define N_WQ 3670016
#define N_WK 1835008
#define N_WV 1835008
#define N_WO 3670016
#define N_SPLIT_TOTAL (N_HS + N_WQ + N_WK + N_WV + N_WO)

__global__ void __launch_bounds__(256)
k_split_all(const float* __restrict__ hs, const float* __restrict__ wq,
            const float* __restrict__ wk, const float* __restrict__ wv,
            const float* __restrict__ wo)
{
    int i = blockIdx.x * 256 + threadIdx.x;
    const float* src;
    h16 *hi, *lo;
    int j = i;
    if (j < N_HS)                 { src = hs; hi = g_hsH; lo = g_hsL; }
    else if ((j -= N_HS) < N_WQ)  { src = wq; hi = g_wqH; lo = nullptr; }
    else if ((j -= N_WQ) < N_WK)  { src = wk; hi = g_wkH; lo = nullptr; }
    else if ((j -= N_WK) < N_WV)  { src = wv; hi = g_wvH; lo = nullptr; }
    else                          { j -= N_WV; src = wo; hi = g_woH; lo = nullptr; }

    float4 v = ((const float4*)src)[j];
    h16 h0 = __float2half(v.x), h1 = __float2half(v.y);
    h16 h2 = __float2half(v.z), h3 = __float2half(v.w);
    __half2 H0; H0.x = h0; H0.y = h1;
    __half2 H1; H1.x = h2; H1.y = h3;
    ((__half2*)hi)[j * 2 + 0] = H0;
    ((__half2*)hi)[j * 2 + 1] = H1;
    if (lo) {
        __half2 L0, L1;
        L0.x = __float2half(v.x - __half2float(h0));
        L0.y = __float2half(v.y - __half2float(h1));
        L1.x = __float2half(v.z - __half2float(h2));
        L1.y = __float2half(v.w - __half2float(h3));
        ((__half2*)lo)[j * 2 + 0] = L0;
        ((__half2*)lo)[j * 2 + 1] = L1;
    }
}

// ---------------- fused RoPE(+split) and V transpose ----------------
#define N_ROPE_BLK ((S_LEN * (NHQ + NKV) * 128) / 256)   // 24576
#define N_VT_BLK   ((S_LEN / 32) * ((NKV * DH) / 32))    // 4096

__global__ void __launch_bounds__(256)
k_rope_vtrans(const float* __restrict__ cosb, const float* __restrict__ sinb)
{
    __shared__ float t[32][33];
    int bid = blockIdx.x;
    if (bid < N_ROPE_BLK) {
        int idx = bid * 256 + threadIdx.x;
        int d = idx & 127;
        int tt = idx >> 7;
        int slot = tt % (NHQ + NKV);
        int s = tt / (NHQ + NKV);

        float c0 = cosb[s * DH + d],       s0 = sinb[s * DH + d];
        float c1 = cosb[s * DH + d + 128], s1 = sinb[s * DH + d + 128];

        if (slot < NHQ) {
            size_t b = (size_t)s * (NHQ * DH) + slot * DH + d;
            float x0 = g_Q[b], x1 = g_Q[b + 128];
            float y0 = x0 * c0 - x1 * s0;
            float y1 = x1 * c1 + x0 * s1;
            h16 h0 = __float2half(y0), h1 = __float2half(y1);
            g_QH[b] = h0;       g_QH[b + 128] = h1;
            g_QL[b] = __float2half(y0 - __half2float(h0));
            g_QL[b + 128] = __float2half(y1 - __half2float(h1));
        } else {
            size_t b = (size_t)s * (NKV * DH) + (slot - NHQ) * DH + d;
            float x0 = g_K[b], x1 = g_K[b + 128];
            float y0 = x0 * c0 - x1 * s0;
            float y1 = x1 * c1 + x0 * s1;
            g_KH[b]       = __float2half(y0);
            g_KH[b + 128] = __float2half(y1);
        }
    } else {
        int b2 = bid - N_ROPE_BLK;
        int bs = (b2 & 63) * 32;
        int bo = (b2 >> 6) * 32;
        int tx = threadIdx.x & 31, ty = threadIdx.x >> 5;
#pragma unroll
        for (int j = 0; j < 32; j += 8)
            t[ty + j][tx] = g_V[(size_t)(bs + ty + j) * (NKV * DH) + bo + tx];
        __syncthreads();
#pragma unroll
        for (int j = 0; j < 32; j += 8) {
            float v = t[tx][ty + j];
            g_VtH[(size_t)(bo + ty + j) * S_LEN + bs + tx] = __float2half(v);
        }
    }
}

// ---------------- band softmax (fast-math) -> P hi only ----------------
__global__ void __launch_bounds__(256)
k_softmax()
{
    int row  = blockIdx.x * 8 + (threadIdx.x >> 5);
    int lane = threadIdx.x & 31;
    int h = row >> 11;
    int q = row & 2047;

    size_t base = ((size_t)h * S_LEN + q) * BANDW;
    const float* p = g_S + base;
    int r  = q >> 7;
    int c0 = ((r - 8 > 0) ? (r - 8) : 0) * 128;
    int kmin = (q - (WINDOW - 1) > 0) ? (q - (WINDOW - 1)) : 0;

    float v[36];
    float m = -1e30f;
#pragma unroll
    for (int i = 0; i < 36; ++i) {
        int j = lane + 32 * i;
        int k = c0 + j;
        float tt;
        if (k >= kmin && k <= q) {
            float x = p[j] * (SCALING / SOFTCAP);
            x = fminf(fmaxf(x, -15.0f), 15.0f);
            float e2 = __expf(2.0f * x);
            tt = SOFTCAP * ((e2 - 1.0f) / (e2 + 1.0f));
        } else {
            tt = -1e30f;
        }
        v[i] = tt;
        m = fmaxf(m, tt);
    }
#pragma unroll
    for (int o = 16; o > 0; o >>= 1)
        m = fmaxf(m, __shfl_xor_sync(0xFFFFFFFFu, m, o));

    float l = 0.0f;
#pragma unroll
    for (int i = 0; i < 36; ++i) {
        v[i] = __expf(v[i] - m);
        l += v[i];
    }
#pragma unroll
    for (int o = 16; o > 0; o >>= 1)
        l += __shfl_xor_sync(0xFFFFFFFFu, l, o);

    float inv = 1.0f / l;
#pragma unroll
    for (int i = 0; i < 36; ++i)
        g_PH[base + lane + 32 * i] = __float2half(v[i] * inv);
}

// ---------------- launch ----------------
extern "C" void kernel_launch(void* const* d_in, const int* in_sizes, int n_in,
                              void* d_out, int out_size)
{
    const float* hs   = (const float*)d_in[0];
    const float* cosb = (const float*)d_in[1];
    const float* sinb = (const float*)d_in[2];
    const float* wq   = (const float*)d_in[3];
    const float* wk   = (const float*)d_in[4];
    const float* wv   = (const float*)d_in[5];
    const float* wo   = (const float*)d_in[6];
    float* out = (float*)d_out;

    cudaFuncSetAttribute(k_gemm_qkv, cudaFuncAttributeMaxDynamicSharedMemorySize, SMEM2);
    cudaFuncSetAttribute(k_gemm_o,   cudaFuncAttributeMaxDynamicSharedMemorySize, SMEM1);
    cudaFuncSetAttribute(k_attn_s,   cudaFuncAttributeMaxDynamicSharedMemorySize, SMEM2);
    cudaFuncSetAttribute(k_attn_pv,  cudaFuncAttributeMaxDynamicSharedMemorySize, SMEM1);

    // fused split of all inputs
    k_split_all<<<N_SPLIT_TOTAL / 256, 256>>>(hs, wq, wk, wv, wo);

    // fused QKV projections (Q/K 2-product, V 1-product)
    k_gemm_qkv<<<dim3(64, S_LEN / 128), 128, SMEM2>>>();

    // RoPE + split and V transpose (single launch)
    k_rope_vtrans<<<N_ROPE_BLK + N_VT_BLK, 256>>>(cosb, sinb);

    // banded scores (2-product)
    k_attn_s<<<dim3(9, S_LEN / 128, NHQ), 128, SMEM2>>>();

    // softcap + mask + softmax -> P hi
    k_softmax<<<(NHQ * S_LEN) / 8, 256>>>();

    // PV (1-product, occ 3) -> AO hi
    k_attn_pv<<<dim3(2, S_LEN / 128, NHQ), 128, SMEM1>>>();

    // output projection (1-product, occ 3)
    k_gemm_o<<<dim3(HID / 128, S_LEN / 128), 128, SMEM1>>>(out);
}